// round 2
// baseline (speedup 1.0000x reference)
#include <cuda_runtime.h>
#include <cstdint>

// Problem constants
#define B_   1024
#define T_   200
#define E_   100
#define H_   200
#define G3_  600      // 3*H
#define NITEMS 100000

// Scratch (device globals; allocation is forbidden)
__device__ float g_S [T_ * B_ * E_];        // state, time-major  [t][b][e]   (~82 MB)
__device__ float g_GI[(size_t)T_ * B_ * G3_]; // gi = x@Wi+bi     [t][b][600] (~492 MB)
__device__ float g_hT[B_ * H_];             // final hidden state [b][200]

typedef unsigned long long ull;

static __device__ __forceinline__ ull pack2(float x, float y) {
    ull r; asm("mov.b64 %0, {%1,%2};" : "=l"(r) : "f"(x), "f"(y)); return r;
}
static __device__ __forceinline__ float2 unpack2(ull v) {
    float2 r; asm("mov.b64 {%0,%1}, %2;" : "=f"(r.x), "=f"(r.y) : "l"(v)); return r;
}
static __device__ __forceinline__ void fma2(ull& d, ull a, ull b) {
    asm("fma.rn.f32x2 %0, %1, %2, %0;" : "+l"(d) : "l"(a), "l"(b));
}

// ---------------------------------------------------------------------------
// K1: state[t][b][e] = embed_q[q[b,t]][e] * embed_f[f[b,t]][e]
// ---------------------------------------------------------------------------
__global__ void k_embed(const int* __restrict__ q, const int* __restrict__ f,
                        const float* __restrict__ eq, const float* __restrict__ ef) {
    int idx = blockIdx.x * blockDim.x + threadIdx.x;
    const int TOT = T_ * B_ * E_;
    if (idx >= TOT) return;
    int t = idx / (B_ * E_);
    int r = idx - t * (B_ * E_);
    int b = r / E_;
    int e = r - b * E_;
    int qi = __ldg(q + b * T_ + t);
    int fi = __ldg(f + b * T_ + t);
    g_S[idx] = __ldg(eq + qi * E_ + e) * __ldg(ef + fi * E_ + e);
}

// ---------------------------------------------------------------------------
// K2: GI[t][b][n] = sum_e state[t][b][e]*Wi[t][e][n] + bi[t][n]
// Tile: M=64 (batch) x N=120, K=100 (2 chunks of 50). 480 threads, micro 4x4.
// grid = (btile=16, ntile=5, t=200)  [x fastest so 16 blocks share the Wi tile]
// ---------------------------------------------------------------------------
__global__ void k_gi(const float* __restrict__ Wi, const float* __restrict__ bi) {
    const int bt = blockIdx.x;   // 0..15
    const int nt = blockIdx.y;   // 0..4
    const int t  = blockIdx.z;   // 0..199

    __shared__ float As[50][68];   // [k][m], padded
    __shared__ float Bs[50][120];  // [k][n]

    const int tid = threadIdx.x;       // 0..479
    const int tx  = tid % 30;          // n-group
    const int ty  = tid / 30;          // m-group

    ull acc[4][2];
    #pragma unroll
    for (int i = 0; i < 4; ++i) { acc[i][0] = 0ULL; acc[i][1] = 0ULL; }

    for (int k0 = 0; k0 < E_; k0 += 50) {
        for (int i = tid; i < 64 * 50; i += 480) {
            int m = i / 50, kk = i - m * 50;
            As[kk][m] = g_S[(t * B_ + bt * 64 + m) * E_ + k0 + kk];
        }
        for (int i = tid; i < 50 * 120; i += 480) {
            int kk = i / 120, nn = i - kk * 120;
            Bs[kk][nn] = Wi[(t * E_ + k0 + kk) * G3_ + nt * 120 + nn];
        }
        __syncthreads();

        #pragma unroll 2
        for (int kk = 0; kk < 50; ++kk) {
            float4 a4 = *(const float4*)&As[kk][ty * 4];
            const ull* bp = (const ull*)&Bs[kk][tx * 4];
            ull b0 = bp[0], b1 = bp[1];
            ull ad;
            ad = pack2(a4.x, a4.x); fma2(acc[0][0], ad, b0); fma2(acc[0][1], ad, b1);
            ad = pack2(a4.y, a4.y); fma2(acc[1][0], ad, b0); fma2(acc[1][1], ad, b1);
            ad = pack2(a4.z, a4.z); fma2(acc[2][0], ad, b0); fma2(acc[2][1], ad, b1);
            ad = pack2(a4.w, a4.w); fma2(acc[3][0], ad, b0); fma2(acc[3][1], ad, b1);
        }
        __syncthreads();
    }

    // epilogue: add bi, store
    #pragma unroll
    for (int i = 0; i < 4; ++i) {
        int row = bt * 64 + ty * 4 + i;
        float* dst = g_GI + ((size_t)t * B_ + row) * G3_;
        #pragma unroll
        for (int c = 0; c < 2; ++c) {
            int col = nt * 120 + tx * 4 + c * 2;
            float2 v = unpack2(acc[i][c]);
            v.x += __ldg(bi + t * G3_ + col);
            v.y += __ldg(bi + t * G3_ + col + 1);
            *(float2*)(dst + col) = v;
        }
    }
}

// ---------------------------------------------------------------------------
// K3: GRU scan. 128 CTAs, each owns 8 batch rows (independent -> no grid sync).
// h kept in SMEM duplicated as f32x2 pairs. Per step:
//   gh[8][600] = h[8][200] @ Wh_t[200][600]   (300 col-pair threads)
//   gate update (all 320 threads)
// ---------------------------------------------------------------------------
__global__ void k_scan(const float* __restrict__ Wh, const float* __restrict__ bhn,
                       const float* __restrict__ init_carry,
                       const float* __restrict__ /*unused*/) {
    __shared__ ull   sh_h2[8 * H_];   // h duplicated {h,h}, [b*200+j]
    __shared__ float sh_gh[8 * G3_];  // gh [b*600 + col]

    const int tid = threadIdx.x;      // 0..319
    const int b0  = blockIdx.x * 8;

    for (int i = tid; i < 8 * H_; i += 320) {
        float v = __ldg(init_carry + (i % H_));
        sh_h2[i] = pack2(v, v);
    }
    __syncthreads();

    for (int t = 0; t < T_; ++t) {
        if (tid < 300) {
            ull acc[8];
            #pragma unroll
            for (int b = 0; b < 8; ++b) acc[b] = 0ULL;

            const ull* wp = (const ull*)(Wh + (size_t)t * H_ * G3_) + tid; // pair col
            #pragma unroll 4
            for (int k = 0; k < H_; ++k) {
                ull w2 = __ldg(wp + k * 300);
                #pragma unroll
                for (int b = 0; b < 8; ++b)
                    fma2(acc[b], sh_h2[b * H_ + k], w2);
            }
            #pragma unroll
            for (int b = 0; b < 8; ++b)
                *(float2*)&sh_gh[b * G3_ + 2 * tid] = unpack2(acc[b]);
        }
        __syncthreads();

        for (int i = tid; i < 8 * H_; i += 320) {
            int b = i / H_, j = i - b * H_;
            const float* gi = g_GI + ((size_t)t * B_ + b0 + b) * G3_;
            float ghr = sh_gh[b * G3_ + j];
            float ghz = sh_gh[b * G3_ + H_ + j];
            float ghn = sh_gh[b * G3_ + 2 * H_ + j];
            float r = 1.f / (1.f + expf(-(__ldg(gi + j) + ghr)));
            float z = 1.f / (1.f + expf(-(__ldg(gi + H_ + j) + ghz)));
            float n = tanhf(__ldg(gi + 2 * H_ + j) + r * (ghn + __ldg(bhn + t * H_ + j)));
            float hold = unpack2(sh_h2[i]).x;
            float hnew = (1.f - z) * n + z * hold;
            sh_h2[i] = pack2(hnew, hnew);
        }
        __syncthreads();
    }

    for (int i = tid; i < 8 * H_; i += 320) {
        int b = i / H_, j = i - b * H_;
        g_hT[(b0 + b) * H_ + j] = unpack2(sh_h2[i]).x;
    }
}

// ---------------------------------------------------------------------------
// K4: out[b][n] = hT[b] . Wout[:,n] + bout[n]
// Tile M=64 x N=128, K=200 (4 chunks of 50). 256 threads, micro 4x8.
// grid = (mtile=16, ntile=782)  [x fastest so 16 blocks share the Wout tile]
// ---------------------------------------------------------------------------
__global__ void k_out(const float* __restrict__ Wout, const float* __restrict__ bout,
                      float* __restrict__ out) {
    const int mt = blockIdx.x;           // 0..15
    const int n0 = blockIdx.y * 128;     // 0..99968

    __shared__ float As[50][68];   // [k][m] padded
    __shared__ float Bs[50][128];  // [k][n]

    const int tid = threadIdx.x;   // 0..255
    const int tx  = tid % 16;      // n-group (8 cols)
    const int ty  = tid / 16;      // m-group (4 rows)

    ull acc[4][4];
    #pragma unroll
    for (int i = 0; i < 4; ++i)
        #pragma unroll
        for (int c = 0; c < 4; ++c) acc[i][c] = 0ULL;

    for (int k0 = 0; k0 < H_; k0 += 50) {
        for (int i = tid; i < 64 * 50; i += 256) {
            int m = i / 50, kk = i - m * 50;
            As[kk][m] = g_hT[(mt * 64 + m) * H_ + k0 + kk];
        }
        for (int i = tid; i < 50 * 128; i += 256) {
            int kk = i / 128, nn = i - kk * 128;
            int gn = n0 + nn;
            Bs[kk][nn] = (gn < NITEMS) ? __ldg(Wout + (size_t)(k0 + kk) * NITEMS + gn) : 0.f;
        }
        __syncthreads();

        #pragma unroll 2
        for (int kk = 0; kk < 50; ++kk) {
            float4 a4 = *(const float4*)&As[kk][ty * 4];
            const ull* bp = (const ull*)&Bs[kk][tx * 8];
            ull b0 = bp[0], b1 = bp[1], b2 = bp[2], b3 = bp[3];
            ull ad;
            ad = pack2(a4.x, a4.x);
            fma2(acc[0][0], ad, b0); fma2(acc[0][1], ad, b1); fma2(acc[0][2], ad, b2); fma2(acc[0][3], ad, b3);
            ad = pack2(a4.y, a4.y);
            fma2(acc[1][0], ad, b0); fma2(acc[1][1], ad, b1); fma2(acc[1][2], ad, b2); fma2(acc[1][3], ad, b3);
            ad = pack2(a4.z, a4.z);
            fma2(acc[2][0], ad, b0); fma2(acc[2][1], ad, b1); fma2(acc[2][2], ad, b2); fma2(acc[2][3], ad, b3);
            ad = pack2(a4.w, a4.w);
            fma2(acc[3][0], ad, b0); fma2(acc[3][1], ad, b1); fma2(acc[3][2], ad, b2); fma2(acc[3][3], ad, b3);
        }
        __syncthreads();
    }

    #pragma unroll
    for (int i = 0; i < 4; ++i) {
        int row = mt * 64 + ty * 4 + i;
        float* dst = out + (size_t)row * NITEMS;
        #pragma unroll
        for (int c = 0; c < 4; ++c) {
            int col = n0 + tx * 8 + c * 2;
            if (col < NITEMS) {   // NITEMS is even -> pair never straddles
                float2 v = unpack2(acc[i][c]);
                v.x += __ldg(bout + col);
                v.y += __ldg(bout + col + 1);
                *(float2*)(dst + col) = v;
            }
        }
    }
}

// ---------------------------------------------------------------------------
extern "C" void kernel_launch(void* const* d_in, const int* in_sizes, int n_in,
                              void* d_out, int out_size) {
    const int*   q    = (const int*)  d_in[0];
    const int*   f    = (const int*)  d_in[1];
    const float* eq   = (const float*)d_in[2];
    const float* ef   = (const float*)d_in[3];
    const float* ic   = (const float*)d_in[4];
    const float* Wi   = (const float*)d_in[5];
    const float* bi   = (const float*)d_in[6];
    const float* Wh   = (const float*)d_in[7];
    const float* bhn  = (const float*)d_in[8];
    const float* Wout = (const float*)d_in[9];
    const float* bout = (const float*)d_in[10];
    float* out = (float*)d_out;

    // K1: embed gather
    {
        const int TOT = T_ * B_ * E_;
        k_embed<<<(TOT + 255) / 256, 256>>>(q, f, eq, ef);
    }
    // K2: GI = x@Wi + bi for all t
    {
        dim3 grid(16, 5, 200);
        k_gi<<<grid, 480>>>(Wi, bi);
    }
    // K3: GRU scan
    {
        k_scan<<<128, 320>>>(Wh, bhn, ic, nullptr);
    }
    // K4: out = hT @ Wout + bout
    {
        dim3 grid(16, (NITEMS + 127) / 128);
        k_out<<<grid, 256>>>(Wout, bout, out);
    }
}

// round 3
// speedup vs baseline: 1.2603x; 1.2603x over previous
#include <cuda_runtime.h>
#include <cstdint>

// Problem constants
#define B_   1024
#define T_   200
#define E_   100
#define H_   200
#define G3_  600      // 3*H
#define NITEMS 100000

// Scratch (device globals; allocation is forbidden)
__device__ float g_GI[(size_t)T_ * B_ * G3_]; // gi = x@Wi+bi  [t][b][600] (~492 MB)
__device__ float g_hT[B_ * H_];               // final hidden state [b][200]

typedef unsigned long long ull;

static __device__ __forceinline__ ull pack2(float x, float y) {
    ull r; asm("mov.b64 %0, {%1,%2};" : "=l"(r) : "f"(x), "f"(y)); return r;
}
static __device__ __forceinline__ float2 unpack2(ull v) {
    float2 r; asm("mov.b64 {%0,%1}, %2;" : "=f"(r.x), "=f"(r.y) : "l"(v)); return r;
}
static __device__ __forceinline__ void fma2(ull& d, ull a, ull b) {
    asm("fma.rn.f32x2 %0, %1, %2, %0;" : "+l"(d) : "l"(a), "l"(b));
}
static __device__ __forceinline__ ull add2(ull a, ull b) {
    ull r; asm("add.rn.f32x2 %0, %1, %2;" : "=l"(r) : "l"(a), "l"(b)); return r;
}

static __device__ __forceinline__ float fast_sigmoid(float x) {
    return __fdividef(1.f, 1.f + __expf(-x));
}
static __device__ __forceinline__ float fast_tanh(float x) {
    x = fminf(fmaxf(x, -15.f), 15.f);
    float p = __expf(2.f * x);
    return __fdividef(p - 1.f, p + 1.f);
}

// ---------------------------------------------------------------------------
// K2 (fused embed+GI): GI[t][b][n] = sum_e (eq[q[b,t]][e]*ef[f[b,t]][e]) * Wi[t][e][n] + bi[t][n]
// Tile M=128 x N=120, K=100 (single chunk). 256 threads, micro 8x8 on 240 threads.
// grid = (btile=8, ntile=5, t=200)
// Dynamic smem: As[100][136] + Bs[100][124]
// ---------------------------------------------------------------------------
#define K2_AP 136
#define K2_BP 124
#define K2_SMEM ((100*K2_AP + 100*K2_BP) * 4)

__global__ void __launch_bounds__(256, 2)
k_gi(const int* __restrict__ q, const int* __restrict__ f,
     const float* __restrict__ eq, const float* __restrict__ ef,
     const float* __restrict__ Wi, const float* __restrict__ bi) {
    extern __shared__ float smem[];
    float* As = smem;                 // [k][m] padded to 136
    float* Bs = smem + 100 * K2_AP;   // [k][n] padded to 124

    const int bt = blockIdx.x;   // 0..7
    const int nt = blockIdx.y;   // 0..4
    const int t  = blockIdx.z;   // 0..199
    const int tid = threadIdx.x; // 0..255
    const int b_base = bt * 128;

    // A tile: fused gather+product, stored transposed [e][m]
    for (int i = tid; i < 128 * 100; i += 256) {
        int m = i / 100, e = i - m * 100;
        int b = b_base + m;
        int qi = __ldg(q + b * T_ + t);
        int fi = __ldg(f + b * T_ + t);
        As[e * K2_AP + m] = __ldg(eq + qi * E_ + e) * __ldg(ef + fi * E_ + e);
    }
    // B tile
    for (int i = tid; i < 100 * 120; i += 256) {
        int kk = i / 120, nn = i - kk * 120;
        Bs[kk * K2_BP + nn] = __ldg(Wi + (size_t)(t * E_ + kk) * G3_ + nt * 120 + nn);
    }
    __syncthreads();

    if (tid < 240) {
        const int tx = tid % 15;   // col group (8 cols)
        const int ty = tid / 15;   // row group (8 rows)

        ull acc[8][4];
        #pragma unroll
        for (int r = 0; r < 8; ++r)
            #pragma unroll
            for (int c = 0; c < 4; ++c) acc[r][c] = 0ULL;

        #pragma unroll 4
        for (int kk = 0; kk < 100; ++kk) {
            const float* ap = &As[kk * K2_AP + ty * 8];
            float4 a0 = *(const float4*)ap;
            float4 a1 = *(const float4*)(ap + 4);
            const ulonglong2* bp = (const ulonglong2*)&Bs[kk * K2_BP + tx * 8];
            ulonglong2 bA = bp[0], bB = bp[1];
            ull ad;
            ad = pack2(a0.x, a0.x); fma2(acc[0][0], ad, bA.x); fma2(acc[0][1], ad, bA.y); fma2(acc[0][2], ad, bB.x); fma2(acc[0][3], ad, bB.y);
            ad = pack2(a0.y, a0.y); fma2(acc[1][0], ad, bA.x); fma2(acc[1][1], ad, bA.y); fma2(acc[1][2], ad, bB.x); fma2(acc[1][3], ad, bB.y);
            ad = pack2(a0.z, a0.z); fma2(acc[2][0], ad, bA.x); fma2(acc[2][1], ad, bA.y); fma2(acc[2][2], ad, bB.x); fma2(acc[2][3], ad, bB.y);
            ad = pack2(a0.w, a0.w); fma2(acc[3][0], ad, bA.x); fma2(acc[3][1], ad, bA.y); fma2(acc[3][2], ad, bB.x); fma2(acc[3][3], ad, bB.y);
            ad = pack2(a1.x, a1.x); fma2(acc[4][0], ad, bA.x); fma2(acc[4][1], ad, bA.y); fma2(acc[4][2], ad, bB.x); fma2(acc[4][3], ad, bB.y);
            ad = pack2(a1.y, a1.y); fma2(acc[5][0], ad, bA.x); fma2(acc[5][1], ad, bA.y); fma2(acc[5][2], ad, bB.x); fma2(acc[5][3], ad, bB.y);
            ad = pack2(a1.z, a1.z); fma2(acc[6][0], ad, bA.x); fma2(acc[6][1], ad, bA.y); fma2(acc[6][2], ad, bB.x); fma2(acc[6][3], ad, bB.y);
            ad = pack2(a1.w, a1.w); fma2(acc[7][0], ad, bA.x); fma2(acc[7][1], ad, bA.y); fma2(acc[7][2], ad, bB.x); fma2(acc[7][3], ad, bB.y);
        }

        // epilogue: add bi, store as 2x float4 per row
        const int col = nt * 120 + tx * 8;
        float4 bi0 = *(const float4*)(bi + t * G3_ + col);
        float4 bi1 = *(const float4*)(bi + t * G3_ + col + 4);
        #pragma unroll
        for (int r = 0; r < 8; ++r) {
            int row = b_base + ty * 8 + r;
            float* dst = g_GI + ((size_t)t * B_ + row) * G3_ + col;
            float2 v0 = unpack2(acc[r][0]), v1 = unpack2(acc[r][1]);
            float2 v2 = unpack2(acc[r][2]), v3 = unpack2(acc[r][3]);
            float4 o0 = make_float4(v0.x + bi0.x, v0.y + bi0.y, v1.x + bi0.z, v1.y + bi0.w);
            float4 o1 = make_float4(v2.x + bi1.x, v2.y + bi1.y, v3.x + bi1.z, v3.y + bi1.w);
            *(float4*)dst = o0;
            *(float4*)(dst + 4) = o1;
        }
    }
}

// ---------------------------------------------------------------------------
// K3: GRU scan. 128 CTAs x 8 batch rows, 320 threads.
// ---------------------------------------------------------------------------
__global__ void __launch_bounds__(320, 1)
k_scan(const float* __restrict__ Wh, const float* __restrict__ bhn,
       const float* __restrict__ init_carry) {
    __shared__ ull   sh_h2[8 * H_];   // h duplicated {h,h}
    __shared__ float sh_gh[8 * G3_];

    const int tid = threadIdx.x;      // 0..319
    const int b0  = blockIdx.x * 8;

    for (int i = tid; i < 8 * H_; i += 320) {
        float v = __ldg(init_carry + (i % H_));
        sh_h2[i] = pack2(v, v);
    }
    __syncthreads();

    for (int t = 0; t < T_; ++t) {
        if (tid < 300) {
            ull acc0[8], acc1[8];
            #pragma unroll
            for (int b = 0; b < 8; ++b) { acc0[b] = 0ULL; acc1[b] = 0ULL; }

            const ull* wp = (const ull*)(Wh + (size_t)t * H_ * G3_) + tid;
            #pragma unroll 2
            for (int k = 0; k < H_; k += 2) {
                ull w0 = __ldg(wp + k * 300);
                ull w1 = __ldg(wp + k * 300 + 300);
                #pragma unroll
                for (int b = 0; b < 8; ++b) {
                    ulonglong2 h2 = *(const ulonglong2*)&sh_h2[b * H_ + k];
                    fma2(acc0[b], h2.x, w0);
                    fma2(acc1[b], h2.y, w1);
                }
            }
            #pragma unroll
            for (int b = 0; b < 8; ++b)
                *(float2*)&sh_gh[b * G3_ + 2 * tid] = unpack2(add2(acc0[b], acc1[b]));
        }
        __syncthreads();

        for (int i = tid; i < 8 * H_; i += 320) {
            int b = i / H_, j = i - b * H_;
            const float* gi = g_GI + ((size_t)t * B_ + b0 + b) * G3_;
            float ghr = sh_gh[b * G3_ + j];
            float ghz = sh_gh[b * G3_ + H_ + j];
            float ghn = sh_gh[b * G3_ + 2 * H_ + j];
            float r = fast_sigmoid(__ldg(gi + j) + ghr);
            float z = fast_sigmoid(__ldg(gi + H_ + j) + ghz);
            float n = fast_tanh(__ldg(gi + 2 * H_ + j) + r * (ghn + __ldg(bhn + t * H_ + j)));
            float hold = unpack2(sh_h2[i]).x;
            float hnew = (1.f - z) * n + z * hold;
            sh_h2[i] = pack2(hnew, hnew);
        }
        __syncthreads();
    }

    for (int i = tid; i < 8 * H_; i += 320) {
        int b = i / H_, j = i - b * H_;
        g_hT[(b0 + b) * H_ + j] = unpack2(sh_h2[i]).x;
    }
}

// ---------------------------------------------------------------------------
// K4: out[b][n] = hT[b] . Wout[:,n] + bout[n]
// Tile M=128 x N=128, K=200 (2 chunks of 100). 256 threads, micro 8x8.
// grid = (mtile=8, ntile=782)
// Dynamic smem: As[100][136] + Bs[100][128]
// ---------------------------------------------------------------------------
#define K4_AP 136
#define K4_SMEM ((100*K4_AP + 100*128) * 4)

__global__ void __launch_bounds__(256, 2)
k_out(const float* __restrict__ Wout, const float* __restrict__ bout,
      float* __restrict__ out) {
    extern __shared__ float smem[];
    float* As = smem;                 // [k][m] padded to 136
    float* Bs = smem + 100 * K4_AP;   // [k][n] 128 wide

    const int mt = blockIdx.x;           // 0..7
    const int n0 = blockIdx.y * 128;
    const int tid = threadIdx.x;
    const int tx = tid % 16;             // col group (8 cols)
    const int ty = tid / 16;             // row group (8 rows)

    ull acc[8][4];
    #pragma unroll
    for (int r = 0; r < 8; ++r)
        #pragma unroll
        for (int c = 0; c < 4; ++c) acc[r][c] = 0ULL;

    for (int k0 = 0; k0 < H_; k0 += 100) {
        for (int i = tid; i < 128 * 100; i += 256) {
            int m = i / 100, kk = i - m * 100;
            As[kk * K4_AP + m] = g_hT[(mt * 128 + m) * H_ + k0 + kk];
        }
        for (int i = tid; i < 100 * 128; i += 256) {
            int kk = i / 128, nn = i - kk * 128;
            int gn = n0 + nn;
            Bs[kk * 128 + nn] = (gn < NITEMS) ? __ldg(Wout + (size_t)(k0 + kk) * NITEMS + gn) : 0.f;
        }
        __syncthreads();

        #pragma unroll 4
        for (int kk = 0; kk < 100; ++kk) {
            const float* ap = &As[kk * K4_AP + ty * 8];
            float4 a0 = *(const float4*)ap;
            float4 a1 = *(const float4*)(ap + 4);
            const ulonglong2* bp = (const ulonglong2*)&Bs[kk * 128 + tx * 8];
            ulonglong2 bA = bp[0], bB = bp[1];
            ull ad;
            ad = pack2(a0.x, a0.x); fma2(acc[0][0], ad, bA.x); fma2(acc[0][1], ad, bA.y); fma2(acc[0][2], ad, bB.x); fma2(acc[0][3], ad, bB.y);
            ad = pack2(a0.y, a0.y); fma2(acc[1][0], ad, bA.x); fma2(acc[1][1], ad, bA.y); fma2(acc[1][2], ad, bB.x); fma2(acc[1][3], ad, bB.y);
            ad = pack2(a0.z, a0.z); fma2(acc[2][0], ad, bA.x); fma2(acc[2][1], ad, bA.y); fma2(acc[2][2], ad, bB.x); fma2(acc[2][3], ad, bB.y);
            ad = pack2(a0.w, a0.w); fma2(acc[3][0], ad, bA.x); fma2(acc[3][1], ad, bA.y); fma2(acc[3][2], ad, bB.x); fma2(acc[3][3], ad, bB.y);
            ad = pack2(a1.x, a1.x); fma2(acc[4][0], ad, bA.x); fma2(acc[4][1], ad, bA.y); fma2(acc[4][2], ad, bB.x); fma2(acc[4][3], ad, bB.y);
            ad = pack2(a1.y, a1.y); fma2(acc[5][0], ad, bA.x); fma2(acc[5][1], ad, bA.y); fma2(acc[5][2], ad, bB.x); fma2(acc[5][3], ad, bB.y);
            ad = pack2(a1.z, a1.z); fma2(acc[6][0], ad, bA.x); fma2(acc[6][1], ad, bA.y); fma2(acc[6][2], ad, bB.x); fma2(acc[6][3], ad, bB.y);
            ad = pack2(a1.w, a1.w); fma2(acc[7][0], ad, bA.x); fma2(acc[7][1], ad, bA.y); fma2(acc[7][2], ad, bB.x); fma2(acc[7][3], ad, bB.y);
        }
        __syncthreads();
    }

    const int col = n0 + tx * 8;
    if (col < NITEMS) {   // col multiple of 8, NITEMS multiple of 8 -> full 8 valid
        float4 b0 = *(const float4*)(bout + col);
        float4 b1 = *(const float4*)(bout + col + 4);
        #pragma unroll
        for (int r = 0; r < 8; ++r) {
            int row = mt * 128 + ty * 8 + r;
            float* dst = out + (size_t)row * NITEMS + col;
            float2 v0 = unpack2(acc[r][0]), v1 = unpack2(acc[r][1]);
            float2 v2 = unpack2(acc[r][2]), v3 = unpack2(acc[r][3]);
            float4 o0 = make_float4(v0.x + b0.x, v0.y + b0.y, v1.x + b0.z, v1.y + b0.w);
            float4 o1 = make_float4(v2.x + b1.x, v2.y + b1.y, v3.x + b1.z, v3.y + b1.w);
            *(float4*)dst = o0;
            *(float4*)(dst + 4) = o1;
        }
    }
}

// ---------------------------------------------------------------------------
extern "C" void kernel_launch(void* const* d_in, const int* in_sizes, int n_in,
                              void* d_out, int out_size) {
    const int*   q    = (const int*)  d_in[0];
    const int*   f    = (const int*)  d_in[1];
    const float* eq   = (const float*)d_in[2];
    const float* ef   = (const float*)d_in[3];
    const float* ic   = (const float*)d_in[4];
    const float* Wi   = (const float*)d_in[5];
    const float* bi   = (const float*)d_in[6];
    const float* Wh   = (const float*)d_in[7];
    const float* bhn  = (const float*)d_in[8];
    const float* Wout = (const float*)d_in[9];
    const float* bout = (const float*)d_in[10];
    float* out = (float*)d_out;

    static bool attr_done = false;
    if (!attr_done) {
        cudaFuncSetAttribute(k_gi,  cudaFuncAttributeMaxDynamicSharedMemorySize, K2_SMEM);
        cudaFuncSetAttribute(k_out, cudaFuncAttributeMaxDynamicSharedMemorySize, K4_SMEM);
        attr_done = true;
    }

    // K2: GI = (gathered state) @ Wi + bi for all t (embed fused into A-tile load)
    {
        dim3 grid(8, 5, 200);
        k_gi<<<grid, 256, K2_SMEM>>>(q, f, eq, ef, Wi, bi);
    }
    // K3: GRU scan
    k_scan<<<128, 320>>>(Wh, bhn, ic);
    // K4: out = hT @ Wout + bout
    {
        dim3 grid(8, (NITEMS + 127) / 128);
        k_out<<<grid, 256, K4_SMEM>>>(Wout, bout, out);
    }
}

// round 4
// speedup vs baseline: 1.8887x; 1.4986x over previous
#include <cuda_runtime.h>
#include <cstdint>

// Problem constants
#define B_   1024
#define T_   200
#define E_   100
#define H_   200
#define G3_  600      // 3*H
#define NITEMS 100000

// Scratch (device globals; allocation is forbidden)
__device__ float g_GI[(size_t)T_ * B_ * G3_]; // gi = x@Wi+bi  [t][b][600] (~492 MB)
__device__ float g_hT[B_ * H_];               // final hidden state [b][200]

typedef unsigned long long ull;

static __device__ __forceinline__ ull pack2(float x, float y) {
    ull r; asm("mov.b64 %0, {%1,%2};" : "=l"(r) : "f"(x), "f"(y)); return r;
}
static __device__ __forceinline__ float2 unpack2(ull v) {
    float2 r; asm("mov.b64 {%0,%1}, %2;" : "=f"(r.x), "=f"(r.y) : "l"(v)); return r;
}
static __device__ __forceinline__ void fma2(ull& d, ull a, ull b) {
    asm("fma.rn.f32x2 %0, %1, %2, %0;" : "+l"(d) : "l"(a), "l"(b));
}
static __device__ __forceinline__ ull add2(ull a, ull b) {
    ull r; asm("add.rn.f32x2 %0, %1, %2;" : "=l"(r) : "l"(a), "l"(b)); return r;
}

static __device__ __forceinline__ float fast_sigmoid(float x) {
    return __fdividef(1.f, 1.f + __expf(-x));
}
static __device__ __forceinline__ float fast_tanh(float x) {
    x = fminf(fmaxf(x, -15.f), 15.f);
    float p = __expf(2.f * x);
    return __fdividef(p - 1.f, p + 1.f);
}

// ---------------------------------------------------------------------------
// K2 (fused embed+GI): GI[t][b][n] = sum_e (eq[q[b,t]][e]*ef[f[b,t]][e]) * Wi[t][e][n] + bi[t][n]
// Tile M=128 x N=120, K=100. 256 threads, micro 8x8 on 240 threads.
// grid = (btile=8, ntile=5, t=200)
// ---------------------------------------------------------------------------
#define K2_AP 136
#define K2_BP 124
#define K2_SMEM ((100*K2_AP + 100*K2_BP) * 4 + 128*2*4)

__global__ void __launch_bounds__(256, 2)
k_gi(const int* __restrict__ q, const int* __restrict__ f,
     const float* __restrict__ eq, const float* __restrict__ ef,
     const float* __restrict__ Wi, const float* __restrict__ bi) {
    extern __shared__ float smem[];
    float* As = smem;                 // [k][m] padded to 136
    float* Bs = smem + 100 * K2_AP;   // [k][n] padded to 124
    int*   sq = (int*)(smem + 100 * K2_AP + 100 * K2_BP);
    int*   sf = sq + 128;

    const int bt = blockIdx.x;   // 0..7
    const int nt = blockIdx.y;   // 0..4
    const int t  = blockIdx.z;   // 0..199
    const int tid = threadIdx.x; // 0..255
    const int b_base = bt * 128;

    if (tid < 128) {
        sq[tid] = __ldg(q + (b_base + tid) * T_ + t);
        sf[tid] = __ldg(f + (b_base + tid) * T_ + t);
    }
    __syncthreads();

    // A tile: fused gather+product, stored transposed [e][m]
    for (int i = tid; i < 128 * 100; i += 256) {
        int m = i / 100, e = i - m * 100;
        As[e * K2_AP + m] = __ldg(eq + sq[m] * E_ + e) * __ldg(ef + sf[m] * E_ + e);
    }
    // B tile
    for (int i = tid; i < 100 * 120; i += 256) {
        int kk = i / 120, nn = i - kk * 120;
        Bs[kk * K2_BP + nn] = __ldg(Wi + (size_t)(t * E_ + kk) * G3_ + nt * 120 + nn);
    }
    __syncthreads();

    if (tid < 240) {
        const int tx = tid % 15;   // col group (8 cols)
        const int ty = tid / 15;   // row group (8 rows)

        ull acc[8][4];
        #pragma unroll
        for (int r = 0; r < 8; ++r)
            #pragma unroll
            for (int c = 0; c < 4; ++c) acc[r][c] = 0ULL;

        #pragma unroll 4
        for (int kk = 0; kk < 100; ++kk) {
            const float* ap = &As[kk * K2_AP + ty * 8];
            float4 a0 = *(const float4*)ap;
            float4 a1 = *(const float4*)(ap + 4);
            const ulonglong2* bp = (const ulonglong2*)&Bs[kk * K2_BP + tx * 8];
            ulonglong2 bA = bp[0], bB = bp[1];
            ull ad;
            ad = pack2(a0.x, a0.x); fma2(acc[0][0], ad, bA.x); fma2(acc[0][1], ad, bA.y); fma2(acc[0][2], ad, bB.x); fma2(acc[0][3], ad, bB.y);
            ad = pack2(a0.y, a0.y); fma2(acc[1][0], ad, bA.x); fma2(acc[1][1], ad, bA.y); fma2(acc[1][2], ad, bB.x); fma2(acc[1][3], ad, bB.y);
            ad = pack2(a0.z, a0.z); fma2(acc[2][0], ad, bA.x); fma2(acc[2][1], ad, bA.y); fma2(acc[2][2], ad, bB.x); fma2(acc[2][3], ad, bB.y);
            ad = pack2(a0.w, a0.w); fma2(acc[3][0], ad, bA.x); fma2(acc[3][1], ad, bA.y); fma2(acc[3][2], ad, bB.x); fma2(acc[3][3], ad, bB.y);
            ad = pack2(a1.x, a1.x); fma2(acc[4][0], ad, bA.x); fma2(acc[4][1], ad, bA.y); fma2(acc[4][2], ad, bB.x); fma2(acc[4][3], ad, bB.y);
            ad = pack2(a1.y, a1.y); fma2(acc[5][0], ad, bA.x); fma2(acc[5][1], ad, bA.y); fma2(acc[5][2], ad, bB.x); fma2(acc[5][3], ad, bB.y);
            ad = pack2(a1.z, a1.z); fma2(acc[6][0], ad, bA.x); fma2(acc[6][1], ad, bA.y); fma2(acc[6][2], ad, bB.x); fma2(acc[6][3], ad, bB.y);
            ad = pack2(a1.w, a1.w); fma2(acc[7][0], ad, bA.x); fma2(acc[7][1], ad, bA.y); fma2(acc[7][2], ad, bB.x); fma2(acc[7][3], ad, bB.y);
        }

        // epilogue: add bi, store as 2x float4 per row
        const int col = nt * 120 + tx * 8;
        float4 bi0 = *(const float4*)(bi + t * G3_ + col);
        float4 bi1 = *(const float4*)(bi + t * G3_ + col + 4);
        #pragma unroll
        for (int r = 0; r < 8; ++r) {
            int row = b_base + ty * 8 + r;
            float* dst = g_GI + ((size_t)t * B_ + row) * G3_ + col;
            float2 v0 = unpack2(acc[r][0]), v1 = unpack2(acc[r][1]);
            float2 v2 = unpack2(acc[r][2]), v3 = unpack2(acc[r][3]);
            float4 o0 = make_float4(v0.x + bi0.x, v0.y + bi0.y, v1.x + bi0.z, v1.y + bi0.w);
            float4 o1 = make_float4(v2.x + bi1.x, v2.y + bi1.y, v3.x + bi1.z, v3.y + bi1.w);
            *(float4*)dst = o0;
            *(float4*)(dst + 4) = o1;
        }
    }
}

// ---------------------------------------------------------------------------
// K3: GRU scan v2. 128 CTAs x 8 batch rows, 640 threads.
//   - 600 GEMM threads: col = tid%300 (pair column), half = tid/300 (k-split)
//   - h stored [k][b] as duplicated f32x2 pairs (broadcast LDS.128)
//   - distance-1 register prefetch of w (4 LDGs in flight / warp)
//   - partial sums of the two k-halves combined through sh_gh
// ---------------------------------------------------------------------------
__global__ void __launch_bounds__(640, 1)
k_scan(const float* __restrict__ Wh, const float* __restrict__ bhn,
       const float* __restrict__ init_carry) {
    __shared__ ull   sh_h2[H_ * 8];   // [k][b] duplicated pairs (12.8 KB)
    __shared__ float sh_gh[8 * G3_];  // gh [b*600 + col]        (19.2 KB)

    const int tid = threadIdx.x;      // 0..639
    const int b0  = blockIdx.x * 8;

    for (int i = tid; i < 8 * H_; i += 640) {
        float v = __ldg(init_carry + (i >> 3));
        sh_h2[i] = pack2(v, v);
    }
    __syncthreads();

    const int  col   = tid % 300;     // pair column (cols 2c, 2c+1)
    const int  half  = tid / 300;     // 0 or 1 (2 => idle tail threads)
    const bool gemm  = (tid < 600);
    const int  kbase = half * 100;

    for (int t = 0; t < T_; ++t) {
        ull acc0[8], acc1[8];
        if (gemm) {
            #pragma unroll
            for (int b = 0; b < 8; ++b) { acc0[b] = 0ULL; acc1[b] = 0ULL; }

            const ull* wp = (const ull*)(Wh + (size_t)t * (H_ * G3_)) + (size_t)kbase * 300 + col;
            ull wc0 = __ldg(wp);
            ull wc1 = __ldg(wp + 300);
            ull wc2 = __ldg(wp + 600);
            ull wc3 = __ldg(wp + 900);
            const ull* wpp = wp + 1200;

            #pragma unroll 1
            for (int k0 = 0; k0 < 100; k0 += 4) {
                ull wn0 = 0, wn1 = 0, wn2 = 0, wn3 = 0;
                if (k0 < 96) {
                    wn0 = __ldg(wpp);
                    wn1 = __ldg(wpp + 300);
                    wn2 = __ldg(wpp + 600);
                    wn3 = __ldg(wpp + 900);
                    wpp += 1200;
                }
                const ulonglong2* hp = (const ulonglong2*)&sh_h2[(kbase + k0) * 8];
                {
                    ulonglong2 hA = hp[0], hB = hp[1], hC = hp[2], hD = hp[3];
                    fma2(acc0[0], hA.x, wc0); fma2(acc0[1], hA.y, wc0);
                    fma2(acc0[2], hB.x, wc0); fma2(acc0[3], hB.y, wc0);
                    fma2(acc0[4], hC.x, wc0); fma2(acc0[5], hC.y, wc0);
                    fma2(acc0[6], hD.x, wc0); fma2(acc0[7], hD.y, wc0);
                }
                {
                    ulonglong2 hA = hp[4], hB = hp[5], hC = hp[6], hD = hp[7];
                    fma2(acc1[0], hA.x, wc1); fma2(acc1[1], hA.y, wc1);
                    fma2(acc1[2], hB.x, wc1); fma2(acc1[3], hB.y, wc1);
                    fma2(acc1[4], hC.x, wc1); fma2(acc1[5], hC.y, wc1);
                    fma2(acc1[6], hD.x, wc1); fma2(acc1[7], hD.y, wc1);
                }
                {
                    ulonglong2 hA = hp[8], hB = hp[9], hC = hp[10], hD = hp[11];
                    fma2(acc0[0], hA.x, wc2); fma2(acc0[1], hA.y, wc2);
                    fma2(acc0[2], hB.x, wc2); fma2(acc0[3], hB.y, wc2);
                    fma2(acc0[4], hC.x, wc2); fma2(acc0[5], hC.y, wc2);
                    fma2(acc0[6], hD.x, wc2); fma2(acc0[7], hD.y, wc2);
                }
                {
                    ulonglong2 hA = hp[12], hB = hp[13], hC = hp[14], hD = hp[15];
                    fma2(acc1[0], hA.x, wc3); fma2(acc1[1], hA.y, wc3);
                    fma2(acc1[2], hB.x, wc3); fma2(acc1[3], hB.y, wc3);
                    fma2(acc1[4], hC.x, wc3); fma2(acc1[5], hC.y, wc3);
                    fma2(acc1[6], hD.x, wc3); fma2(acc1[7], hD.y, wc3);
                }
                wc0 = wn0; wc1 = wn1; wc2 = wn2; wc3 = wn3;
            }

            if (half == 1) {
                #pragma unroll
                for (int b = 0; b < 8; ++b)
                    *(float2*)&sh_gh[b * G3_ + 2 * col] = unpack2(add2(acc0[b], acc1[b]));
            }
        }
        __syncthreads();

        if (gemm && half == 0) {
            #pragma unroll
            for (int b = 0; b < 8; ++b) {
                float2* p = (float2*)&sh_gh[b * G3_ + 2 * col];
                float2 o = *p;
                float2 m = unpack2(add2(acc0[b], acc1[b]));
                o.x += m.x; o.y += m.y;
                *p = o;
            }
        }
        __syncthreads();

        // gate phase: 1600 elements over 640 threads
        for (int i = tid; i < 8 * H_; i += 640) {
            int b = i / H_, j = i - b * H_;
            const float* gi = g_GI + ((size_t)t * B_ + b0 + b) * G3_;
            float ghr = sh_gh[b * G3_ + j];
            float ghz = sh_gh[b * G3_ + H_ + j];
            float ghn = sh_gh[b * G3_ + 2 * H_ + j];
            float r = fast_sigmoid(__ldg(gi + j) + ghr);
            float z = fast_sigmoid(__ldg(gi + H_ + j) + ghz);
            float n = fast_tanh(__ldg(gi + 2 * H_ + j) + r * (ghn + __ldg(bhn + t * H_ + j)));
            float hold = unpack2(sh_h2[j * 8 + b]).x;
            float hnew = (1.f - z) * n + z * hold;
            sh_h2[j * 8 + b] = pack2(hnew, hnew);
        }
        __syncthreads();
    }

    for (int i = tid; i < 8 * H_; i += 640) {
        int b = i / H_, j = i - b * H_;
        g_hT[(b0 + b) * H_ + j] = unpack2(sh_h2[j * 8 + b]).x;
    }
}

// ---------------------------------------------------------------------------
// K4: out[b][n] = hT[b] . Wout[:,n] + bout[n]
// Tile M=128 x N=128, K=200 (2 chunks of 100). 256 threads, micro 8x8.
// ---------------------------------------------------------------------------
#define K4_AP 136
#define K4_SMEM ((100*K4_AP + 100*128) * 4)

__global__ void __launch_bounds__(256, 2)
k_out(const float* __restrict__ Wout, const float* __restrict__ bout,
      float* __restrict__ out) {
    extern __shared__ float smem[];
    float* As = smem;                 // [k][m] padded to 136
    float* Bs = smem + 100 * K4_AP;   // [k][n] 128 wide

    const int mt = blockIdx.x;           // 0..7
    const int n0 = blockIdx.y * 128;
    const int tid = threadIdx.x;
    const int tx = tid % 16;             // col group (8 cols)
    const int ty = tid / 16;             // row group (8 rows)

    ull acc[8][4];
    #pragma unroll
    for (int r = 0; r < 8; ++r)
        #pragma unroll
        for (int c = 0; c < 4; ++c) acc[r][c] = 0ULL;

    for (int k0 = 0; k0 < H_; k0 += 100) {
        for (int i = tid; i < 128 * 100; i += 256) {
            int m = i / 100, kk = i - m * 100;
            As[kk * K4_AP + m] = g_hT[(mt * 128 + m) * H_ + k0 + kk];
        }
        for (int i = tid; i < 100 * 128; i += 256) {
            int kk = i / 128, nn = i - kk * 128;
            int gn = n0 + nn;
            Bs[kk * 128 + nn] = (gn < NITEMS) ? __ldg(Wout + (size_t)(k0 + kk) * NITEMS + gn) : 0.f;
        }
        __syncthreads();

        #pragma unroll 4
        for (int kk = 0; kk < 100; ++kk) {
            const float* ap = &As[kk * K4_AP + ty * 8];
            float4 a0 = *(const float4*)ap;
            float4 a1 = *(const float4*)(ap + 4);
            const ulonglong2* bp = (const ulonglong2*)&Bs[kk * 128 + tx * 8];
            ulonglong2 bA = bp[0], bB = bp[1];
            ull ad;
            ad = pack2(a0.x, a0.x); fma2(acc[0][0], ad, bA.x); fma2(acc[0][1], ad, bA.y); fma2(acc[0][2], ad, bB.x); fma2(acc[0][3], ad, bB.y);
            ad = pack2(a0.y, a0.y); fma2(acc[1][0], ad, bA.x); fma2(acc[1][1], ad, bA.y); fma2(acc[1][2], ad, bB.x); fma2(acc[1][3], ad, bB.y);
            ad = pack2(a0.z, a0.z); fma2(acc[2][0], ad, bA.x); fma2(acc[2][1], ad, bA.y); fma2(acc[2][2], ad, bB.x); fma2(acc[2][3], ad, bB.y);
            ad = pack2(a0.w, a0.w); fma2(acc[3][0], ad, bA.x); fma2(acc[3][1], ad, bA.y); fma2(acc[3][2], ad, bB.x); fma2(acc[3][3], ad, bB.y);
            ad = pack2(a1.x, a1.x); fma2(acc[4][0], ad, bA.x); fma2(acc[4][1], ad, bA.y); fma2(acc[4][2], ad, bB.x); fma2(acc[4][3], ad, bB.y);
            ad = pack2(a1.y, a1.y); fma2(acc[5][0], ad, bA.x); fma2(acc[5][1], ad, bA.y); fma2(acc[5][2], ad, bB.x); fma2(acc[5][3], ad, bB.y);
            ad = pack2(a1.z, a1.z); fma2(acc[6][0], ad, bA.x); fma2(acc[6][1], ad, bA.y); fma2(acc[6][2], ad, bB.x); fma2(acc[6][3], ad, bB.y);
            ad = pack2(a1.w, a1.w); fma2(acc[7][0], ad, bA.x); fma2(acc[7][1], ad, bA.y); fma2(acc[7][2], ad, bB.x); fma2(acc[7][3], ad, bB.y);
        }
        __syncthreads();
    }

    const int colo = n0 + tx * 8;
    if (colo < NITEMS) {
        float4 b0v = *(const float4*)(bout + colo);
        float4 b1v = *(const float4*)(bout + colo + 4);
        #pragma unroll
        for (int r = 0; r < 8; ++r) {
            int row = mt * 128 + ty * 8 + r;
            float* dst = out + (size_t)row * NITEMS + colo;
            float2 v0 = unpack2(acc[r][0]), v1 = unpack2(acc[r][1]);
            float2 v2 = unpack2(acc[r][2]), v3 = unpack2(acc[r][3]);
            float4 o0 = make_float4(v0.x + b0v.x, v0.y + b0v.y, v1.x + b0v.z, v1.y + b0v.w);
            float4 o1 = make_float4(v2.x + b1v.x, v2.y + b1v.y, v3.x + b1v.z, v3.y + b1v.w);
            *(float4*)dst = o0;
            *(float4*)(dst + 4) = o1;
        }
    }
}

// ---------------------------------------------------------------------------
extern "C" void kernel_launch(void* const* d_in, const int* in_sizes, int n_in,
                              void* d_out, int out_size) {
    const int*   q    = (const int*)  d_in[0];
    const int*   f    = (const int*)  d_in[1];
    const float* eq   = (const float*)d_in[2];
    const float* ef   = (const float*)d_in[3];
    const float* ic   = (const float*)d_in[4];
    const float* Wi   = (const float*)d_in[5];
    const float* bi   = (const float*)d_in[6];
    const float* Wh   = (const float*)d_in[7];
    const float* bhn  = (const float*)d_in[8];
    const float* Wout = (const float*)d_in[9];
    const float* bout = (const float*)d_in[10];
    float* out = (float*)d_out;

    static bool attr_done = false;
    if (!attr_done) {
        cudaFuncSetAttribute(k_gi,  cudaFuncAttributeMaxDynamicSharedMemorySize, K2_SMEM);
        cudaFuncSetAttribute(k_out, cudaFuncAttributeMaxDynamicSharedMemorySize, K4_SMEM);
        attr_done = true;
    }

    // K2: GI = (gathered state) @ Wi + bi for all t (embed fused into A-tile load)
    {
        dim3 grid(8, 5, 200);
        k_gi<<<grid, 256, K2_SMEM>>>(q, f, eq, ef, Wi, bi);
    }
    // K3: GRU scan
    k_scan<<<128, 640>>>(Wh, bhn, ic);
    // K4: out = hT @ Wout + bout
    {
        dim3 grid(8, (NITEMS + 127) / 128);
        k_out<<<grid, 256, K4_SMEM>>>(Wout, bout, out);
    }
}

// round 6
// speedup vs baseline: 2.1144x; 1.1195x over previous
#include <cuda_runtime.h>
#include <cuda_bf16.h>
#include <cstdint>

// Problem constants
#define B_   1024
#define T_   200
#define E_   100
#define H_   200
#define G3_  600      // 3*H
#define NITEMS 100000

#define KPAD 256             // K padded for tensor path
#define NT2  782             // ceil(100000/128)
#define NPADW (NT2*128)      // 100096

// Scratch (device globals; allocation is forbidden)
__device__ float g_GI[(size_t)T_ * B_ * G3_]; // gi = x@Wi+bi  [t][b][600] (~492 MB)
__device__ float g_hT[B_ * H_];               // final hidden state [b][200]

// bf16 hi/lo operands for the mma.sync output GEMM
__device__ __nv_bfloat16 g_w_hi[(size_t)KPAD * NPADW];  // [k][n] 51.2 MB
__device__ __nv_bfloat16 g_w_lo[(size_t)KPAD * NPADW];
__device__ __nv_bfloat16 g_h_hi[B_ * KPAD];             // [m][k]
__device__ __nv_bfloat16 g_h_lo[B_ * KPAD];

typedef unsigned long long ull;

static __device__ __forceinline__ ull pack2(float x, float y) {
    ull r; asm("mov.b64 %0, {%1,%2};" : "=l"(r) : "f"(x), "f"(y)); return r;
}
static __device__ __forceinline__ float2 unpack2(ull v) {
    float2 r; asm("mov.b64 {%0,%1}, %2;" : "=f"(r.x), "=f"(r.y) : "l"(v)); return r;
}
static __device__ __forceinline__ void fma2(ull& d, ull a, ull b) {
    asm("fma.rn.f32x2 %0, %1, %2, %0;" : "+l"(d) : "l"(a), "l"(b));
}
static __device__ __forceinline__ ull add2(ull a, ull b) {
    ull r; asm("add.rn.f32x2 %0, %1, %2;" : "=l"(r) : "l"(a), "l"(b)); return r;
}
static __device__ __forceinline__ float fast_sigmoid(float x) {
    return __fdividef(1.f, 1.f + __expf(-x));
}
static __device__ __forceinline__ float fast_tanh(float x) {
    x = fminf(fmaxf(x, -15.f), 15.f);
    float p = __expf(2.f * x);
    return __fdividef(p - 1.f, p + 1.f);
}
static __device__ __forceinline__ uint32_t smem_u32(const void* p) {
    uint32_t a;
    asm("{ .reg .u64 t; cvta.to.shared.u64 t, %1; cvt.u32.u64 %0, t; }" : "=r"(a) : "l"(p));
    return a;
}

// ---------------- mma.sync helpers (portable HMMA, sm_80+) ----------------
static __device__ __forceinline__ void ldmA(uint32_t* r, uint32_t addr) {
    asm volatile("ldmatrix.sync.aligned.m8n8.x4.shared.b16 {%0,%1,%2,%3}, [%4];"
        : "=r"(r[0]), "=r"(r[1]), "=r"(r[2]), "=r"(r[3]) : "r"(addr));
}
static __device__ __forceinline__ void ldmBT(uint32_t* r, uint32_t addr) {
    asm volatile("ldmatrix.sync.aligned.m8n8.x4.trans.shared.b16 {%0,%1,%2,%3}, [%4];"
        : "=r"(r[0]), "=r"(r[1]), "=r"(r[2]), "=r"(r[3]) : "r"(addr));
}
static __device__ __forceinline__ void mma_bf16(float* c, const uint32_t* a, const uint32_t* b) {
    asm volatile("mma.sync.aligned.m16n8k16.row.col.f32.bf16.bf16.f32 "
        "{%0,%1,%2,%3}, {%4,%5,%6,%7}, {%8,%9}, {%0,%1,%2,%3};"
        : "+f"(c[0]), "+f"(c[1]), "+f"(c[2]), "+f"(c[3])
        : "r"(a[0]), "r"(a[1]), "r"(a[2]), "r"(a[3]), "r"(b[0]), "r"(b[1]));
}

// ---------------------------------------------------------------------------
// K2 (fused embed+GI): GI[t][b][n] = sum_e (eq[q]*ef[f]) * Wi[t][e][n] + bi[t][n]
// ---------------------------------------------------------------------------
#define K2_AP 136
#define K2_BP 124
#define K2_SMEM ((100*K2_AP + 100*K2_BP) * 4 + 128*2*4)

__global__ void __launch_bounds__(256, 2)
k_gi(const int* __restrict__ q, const int* __restrict__ f,
     const float* __restrict__ eq, const float* __restrict__ ef,
     const float* __restrict__ Wi, const float* __restrict__ bi) {
    extern __shared__ float smem[];
    float* As = smem;
    float* Bs = smem + 100 * K2_AP;
    int*   sq = (int*)(smem + 100 * K2_AP + 100 * K2_BP);
    int*   sf = sq + 128;

    const int bt = blockIdx.x;
    const int nt = blockIdx.y;
    const int t  = blockIdx.z;
    const int tid = threadIdx.x;
    const int b_base = bt * 128;

    if (tid < 128) {
        sq[tid] = __ldg(q + (b_base + tid) * T_ + t);
        sf[tid] = __ldg(f + (b_base + tid) * T_ + t);
    }
    __syncthreads();

    for (int i = tid; i < 128 * 100; i += 256) {
        int m = i / 100, e = i - m * 100;
        As[e * K2_AP + m] = __ldg(eq + sq[m] * E_ + e) * __ldg(ef + sf[m] * E_ + e);
    }
    for (int i = tid; i < 100 * 120; i += 256) {
        int kk = i / 120, nn = i - kk * 120;
        Bs[kk * K2_BP + nn] = __ldg(Wi + (size_t)(t * E_ + kk) * G3_ + nt * 120 + nn);
    }
    __syncthreads();

    if (tid < 240) {
        const int tx = tid % 15;
        const int ty = tid / 15;

        ull acc[8][4];
        #pragma unroll
        for (int r = 0; r < 8; ++r)
            #pragma unroll
            for (int c = 0; c < 4; ++c) acc[r][c] = 0ULL;

        #pragma unroll 4
        for (int kk = 0; kk < 100; ++kk) {
            const float* ap = &As[kk * K2_AP + ty * 8];
            float4 a0 = *(const float4*)ap;
            float4 a1 = *(const float4*)(ap + 4);
            const ulonglong2* bp = (const ulonglong2*)&Bs[kk * K2_BP + tx * 8];
            ulonglong2 bA = bp[0], bB = bp[1];
            ull ad;
            ad = pack2(a0.x, a0.x); fma2(acc[0][0], ad, bA.x); fma2(acc[0][1], ad, bA.y); fma2(acc[0][2], ad, bB.x); fma2(acc[0][3], ad, bB.y);
            ad = pack2(a0.y, a0.y); fma2(acc[1][0], ad, bA.x); fma2(acc[1][1], ad, bA.y); fma2(acc[1][2], ad, bB.x); fma2(acc[1][3], ad, bB.y);
            ad = pack2(a0.z, a0.z); fma2(acc[2][0], ad, bA.x); fma2(acc[2][1], ad, bA.y); fma2(acc[2][2], ad, bB.x); fma2(acc[2][3], ad, bB.y);
            ad = pack2(a0.w, a0.w); fma2(acc[3][0], ad, bA.x); fma2(acc[3][1], ad, bA.y); fma2(acc[3][2], ad, bB.x); fma2(acc[3][3], ad, bB.y);
            ad = pack2(a1.x, a1.x); fma2(acc[4][0], ad, bA.x); fma2(acc[4][1], ad, bA.y); fma2(acc[4][2], ad, bB.x); fma2(acc[4][3], ad, bB.y);
            ad = pack2(a1.y, a1.y); fma2(acc[5][0], ad, bA.x); fma2(acc[5][1], ad, bA.y); fma2(acc[5][2], ad, bB.x); fma2(acc[5][3], ad, bB.y);
            ad = pack2(a1.z, a1.z); fma2(acc[6][0], ad, bA.x); fma2(acc[6][1], ad, bA.y); fma2(acc[6][2], ad, bB.x); fma2(acc[6][3], ad, bB.y);
            ad = pack2(a1.w, a1.w); fma2(acc[7][0], ad, bA.x); fma2(acc[7][1], ad, bA.y); fma2(acc[7][2], ad, bB.x); fma2(acc[7][3], ad, bB.y);
        }

        const int col = nt * 120 + tx * 8;
        float4 bi0 = *(const float4*)(bi + t * G3_ + col);
        float4 bi1 = *(const float4*)(bi + t * G3_ + col + 4);
        #pragma unroll
        for (int r = 0; r < 8; ++r) {
            int row = b_base + ty * 8 + r;
            float* dst = g_GI + ((size_t)t * B_ + row) * G3_ + col;
            float2 v0 = unpack2(acc[r][0]), v1 = unpack2(acc[r][1]);
            float2 v2 = unpack2(acc[r][2]), v3 = unpack2(acc[r][3]);
            *(float4*)dst       = make_float4(v0.x + bi0.x, v0.y + bi0.y, v1.x + bi0.z, v1.y + bi0.w);
            *(float4*)(dst + 4) = make_float4(v2.x + bi1.x, v2.y + bi1.y, v3.x + bi1.z, v3.y + bi1.w);
        }
    }
}

// ---------------------------------------------------------------------------
// K3: GRU scan (round-4 passing version, unchanged)
// ---------------------------------------------------------------------------
__global__ void __launch_bounds__(640, 1)
k_scan(const float* __restrict__ Wh, const float* __restrict__ bhn,
       const float* __restrict__ init_carry) {
    __shared__ ull   sh_h2[H_ * 8];
    __shared__ float sh_gh[8 * G3_];

    const int tid = threadIdx.x;
    const int b0  = blockIdx.x * 8;

    for (int i = tid; i < 8 * H_; i += 640) {
        float v = __ldg(init_carry + (i >> 3));
        sh_h2[i] = pack2(v, v);
    }
    __syncthreads();

    const int  col   = tid % 300;
    const int  half  = tid / 300;
    const bool gemm  = (tid < 600);
    const int  kbase = half * 100;

    for (int t = 0; t < T_; ++t) {
        ull acc0[8], acc1[8];
        if (gemm) {
            #pragma unroll
            for (int b = 0; b < 8; ++b) { acc0[b] = 0ULL; acc1[b] = 0ULL; }

            const ull* wp = (const ull*)(Wh + (size_t)t * (H_ * G3_)) + (size_t)kbase * 300 + col;
            ull wc0 = __ldg(wp);
            ull wc1 = __ldg(wp + 300);
            ull wc2 = __ldg(wp + 600);
            ull wc3 = __ldg(wp + 900);
            const ull* wpp = wp + 1200;

            #pragma unroll 1
            for (int k0 = 0; k0 < 100; k0 += 4) {
                ull wn0 = 0, wn1 = 0, wn2 = 0, wn3 = 0;
                if (k0 < 96) {
                    wn0 = __ldg(wpp);
                    wn1 = __ldg(wpp + 300);
                    wn2 = __ldg(wpp + 600);
                    wn3 = __ldg(wpp + 900);
                    wpp += 1200;
                }
                const ulonglong2* hp = (const ulonglong2*)&sh_h2[(kbase + k0) * 8];
                {
                    ulonglong2 hA = hp[0], hB = hp[1], hC = hp[2], hD = hp[3];
                    fma2(acc0[0], hA.x, wc0); fma2(acc0[1], hA.y, wc0);
                    fma2(acc0[2], hB.x, wc0); fma2(acc0[3], hB.y, wc0);
                    fma2(acc0[4], hC.x, wc0); fma2(acc0[5], hC.y, wc0);
                    fma2(acc0[6], hD.x, wc0); fma2(acc0[7], hD.y, wc0);
                }
                {
                    ulonglong2 hA = hp[4], hB = hp[5], hC = hp[6], hD = hp[7];
                    fma2(acc1[0], hA.x, wc1); fma2(acc1[1], hA.y, wc1);
                    fma2(acc1[2], hB.x, wc1); fma2(acc1[3], hB.y, wc1);
                    fma2(acc1[4], hC.x, wc1); fma2(acc1[5], hC.y, wc1);
                    fma2(acc1[6], hD.x, wc1); fma2(acc1[7], hD.y, wc1);
                }
                {
                    ulonglong2 hA = hp[8], hB = hp[9], hC = hp[10], hD = hp[11];
                    fma2(acc0[0], hA.x, wc2); fma2(acc0[1], hA.y, wc2);
                    fma2(acc0[2], hB.x, wc2); fma2(acc0[3], hB.y, wc2);
                    fma2(acc0[4], hC.x, wc2); fma2(acc0[5], hC.y, wc2);
                    fma2(acc0[6], hD.x, wc2); fma2(acc0[7], hD.y, wc2);
                }
                {
                    ulonglong2 hA = hp[12], hB = hp[13], hC = hp[14], hD = hp[15];
                    fma2(acc1[0], hA.x, wc3); fma2(acc1[1], hA.y, wc3);
                    fma2(acc1[2], hB.x, wc3); fma2(acc1[3], hB.y, wc3);
                    fma2(acc1[4], hC.x, wc3); fma2(acc1[5], hC.y, wc3);
                    fma2(acc1[6], hD.x, wc3); fma2(acc1[7], hD.y, wc3);
                }
                wc0 = wn0; wc1 = wn1; wc2 = wn2; wc3 = wn3;
            }

            if (half == 1) {
                #pragma unroll
                for (int b = 0; b < 8; ++b)
                    *(float2*)&sh_gh[b * G3_ + 2 * col] = unpack2(add2(acc0[b], acc1[b]));
            }
        }
        __syncthreads();

        if (gemm && half == 0) {
            #pragma unroll
            for (int b = 0; b < 8; ++b) {
                float2* p = (float2*)&sh_gh[b * G3_ + 2 * col];
                float2 o = *p;
                float2 m = unpack2(add2(acc0[b], acc1[b]));
                o.x += m.x; o.y += m.y;
                *p = o;
            }
        }
        __syncthreads();

        for (int i = tid; i < 8 * H_; i += 640) {
            int b = i / H_, j = i - b * H_;
            const float* gi = g_GI + ((size_t)t * B_ + b0 + b) * G3_;
            float ghr = sh_gh[b * G3_ + j];
            float ghz = sh_gh[b * G3_ + H_ + j];
            float ghn = sh_gh[b * G3_ + 2 * H_ + j];
            float r = fast_sigmoid(__ldg(gi + j) + ghr);
            float z = fast_sigmoid(__ldg(gi + H_ + j) + ghz);
            float n = fast_tanh(__ldg(gi + 2 * H_ + j) + r * (ghn + __ldg(bhn + t * H_ + j)));
            float hold = unpack2(sh_h2[j * 8 + b]).x;
            float hnew = (1.f - z) * n + z * hold;
            sh_h2[j * 8 + b] = pack2(hnew, hnew);
        }
        __syncthreads();
    }

    for (int i = tid; i < 8 * H_; i += 640) {
        int b = i / H_, j = i - b * H_;
        g_hT[(b0 + b) * H_ + j] = unpack2(sh_h2[j * 8 + b]).x;
    }
}

// ---------------------------------------------------------------------------
// Conversions to bf16 hi/lo
// ---------------------------------------------------------------------------
__global__ void k_cvt_w(const float* __restrict__ Wout) {
    int nb = blockIdx.x * 256 + threadIdx.x;   // n/8 block
    int k  = blockIdx.y;                        // 0..255
    if (nb >= NPADW / 8) return;
    int n = nb * 8;

    unsigned short hs[8], ls[8];
    if (k < H_ && n + 7 < NITEMS) {
        const float4* src = (const float4*)(Wout + (size_t)k * NITEMS + n);
        float4 v0 = __ldg(src), v1 = __ldg(src + 1);
        float vv[8] = {v0.x, v0.y, v0.z, v0.w, v1.x, v1.y, v1.z, v1.w};
        #pragma unroll
        for (int j = 0; j < 8; ++j) {
            __nv_bfloat16 h = __float2bfloat16(vv[j]);
            hs[j] = __bfloat16_as_ushort(h);
            ls[j] = __bfloat16_as_ushort(__float2bfloat16(vv[j] - __bfloat162float(h)));
        }
    } else {
        #pragma unroll
        for (int j = 0; j < 8; ++j) {
            float v = (k < H_ && n + j < NITEMS) ? __ldg(Wout + (size_t)k * NITEMS + n + j) : 0.f;
            __nv_bfloat16 h = __float2bfloat16(v);
            hs[j] = __bfloat16_as_ushort(h);
            ls[j] = __bfloat16_as_ushort(__float2bfloat16(v - __bfloat162float(h)));
        }
    }
    union { unsigned short u[8]; uint4 v; } ph, pl;
    #pragma unroll
    for (int j = 0; j < 8; ++j) { ph.u[j] = hs[j]; pl.u[j] = ls[j]; }
    *(uint4*)(g_w_hi + (size_t)k * NPADW + n) = ph.v;
    *(uint4*)(g_w_lo + (size_t)k * NPADW + n) = pl.v;
}

__global__ void k_cvt_h() {
    int idx = blockIdx.x * 256 + threadIdx.x;   // 1024 * 32
    if (idx >= B_ * 32) return;
    int m = idx >> 5, k8 = idx & 31;
    int k0 = k8 * 8;

    unsigned short hs[8], ls[8];
    #pragma unroll
    for (int j = 0; j < 8; ++j) {
        int k = k0 + j;
        float v = (k < H_) ? g_hT[m * H_ + k] : 0.f;
        __nv_bfloat16 h = __float2bfloat16(v);
        hs[j] = __bfloat16_as_ushort(h);
        ls[j] = __bfloat16_as_ushort(__float2bfloat16(v - __bfloat162float(h)));
    }
    union { unsigned short u[8]; uint4 v; } ph, pl;
    #pragma unroll
    for (int j = 0; j < 8; ++j) { ph.u[j] = hs[j]; pl.u[j] = ls[j]; }
    *(uint4*)(g_h_hi + m * KPAD + k0) = ph.v;
    *(uint4*)(g_h_lo + m * KPAD + k0) = pl.v;
}

// ---------------------------------------------------------------------------
// K4 mma.sync: out[1024][100000] = hT @ Wout + bout, bf16 hi/lo 3-pass.
// BM=128, BN=128, BK=64 (4 chunks of KPAD=256). 8 warps: 2 (m) x 4 (n),
// warp tile 64x32 = 4x4 m16n8 frags. grid = (8 mtiles, 782 ntiles).
// ---------------------------------------------------------------------------
#define ASTR 72     // A smem row stride (bf16)
#define BSTR 136    // B smem row stride (bf16)
#define MMA_SMEM ((2*128*ASTR + 2*64*BSTR) * 2)   // 71680 B

__global__ void __launch_bounds__(256, 1)
k_out_mma(const float* __restrict__ bout, float* __restrict__ out) {
    extern __shared__ __nv_bfloat16 smem_bf[];
    __nv_bfloat16* sAh = smem_bf;                   // [128][ASTR]
    __nv_bfloat16* sAl = sAh + 128 * ASTR;
    __nv_bfloat16* sBh = sAl + 128 * ASTR;          // [64][BSTR]
    __nv_bfloat16* sBl = sBh + 64 * BSTR;

    const int tid  = threadIdx.x;
    const int wid  = tid >> 5, lane = tid & 31;
    const int mt   = blockIdx.x;        // 0..7
    const int nt   = blockIdx.y;        // 0..781
    const int wm   = wid & 1;           // m half (64)
    const int wn   = wid >> 1;          // n quarter (32)

    float acc[4][4][4];
    #pragma unroll
    for (int i = 0; i < 4; ++i)
        #pragma unroll
        for (int j = 0; j < 4; ++j)
            #pragma unroll
            for (int c = 0; c < 4; ++c) acc[i][j][c] = 0.f;

    const uint32_t sAh32 = smem_u32(sAh), sAl32 = smem_u32(sAl);
    const uint32_t sBh32 = smem_u32(sBh), sBl32 = smem_u32(sBl);

    for (int kc = 0; kc < 4; ++kc) {
        // Load A tiles: 128 x 64 bf16 per split (1024 uint4 each)
        for (int i = tid; i < 1024; i += 256) {
            int m = i >> 3, kb = i & 7;
            size_t src = (size_t)(mt * 128 + m) * KPAD + kc * 64 + kb * 8;
            *(uint4*)(sAh + m * ASTR + kb * 8) = *(const uint4*)(g_h_hi + src);
            *(uint4*)(sAl + m * ASTR + kb * 8) = *(const uint4*)(g_h_lo + src);
        }
        // Load B tiles: 64 x 128 bf16 per split
        for (int i = tid; i < 1024; i += 256) {
            int k = i >> 4, nb = i & 15;
            size_t src = (size_t)(kc * 64 + k) * NPADW + nt * 128 + nb * 8;
            *(uint4*)(sBh + k * BSTR + nb * 8) = *(const uint4*)(g_w_hi + src);
            *(uint4*)(sBl + k * BSTR + nb * 8) = *(const uint4*)(g_w_lo + src);
        }
        __syncthreads();

        #pragma unroll
        for (int ks = 0; ks < 4; ++ks) {
            // A fragments: 4 m-frags x (hi, lo)
            uint32_t Ah[4][4], Al[4][4];
            #pragma unroll
            for (int fm = 0; fm < 4; ++fm) {
                uint32_t off = ((wm * 64 + fm * 16 + (lane & 15)) * ASTR
                                + ks * 16 + (lane >> 4) * 8) * 2;
                ldmA(Ah[fm], sAh32 + off);
                ldmA(Al[fm], sAl32 + off);
            }
            // B fragments: 2x ldmatrix.x4.trans per split -> 4 n8-frags
            uint32_t Bh[4][2], Bl[4][2];
            #pragma unroll
            for (int fb = 0; fb < 2; ++fb) {
                uint32_t off = ((ks * 16 + (lane & 15)) * BSTR
                                + wn * 32 + fb * 16 + (lane >> 4) * 8) * 2;
                uint32_t r[4];
                ldmBT(r, sBh32 + off);
                Bh[fb*2][0] = r[0]; Bh[fb*2][1] = r[1];
                Bh[fb*2+1][0] = r[2]; Bh[fb*2+1][1] = r[3];
                ldmBT(r, sBl32 + off);
                Bl[fb*2][0] = r[0]; Bl[fb*2][1] = r[1];
                Bl[fb*2+1][0] = r[2]; Bl[fb*2+1][1] = r[3];
            }
            // 3-pass accumulate: hi*hi + hi*lo + lo*hi
            #pragma unroll
            for (int fm = 0; fm < 4; ++fm)
                #pragma unroll
                for (int fn = 0; fn < 4; ++fn) {
                    mma_bf16(acc[fm][fn], Ah[fm], Bh[fn]);
                    mma_bf16(acc[fm][fn], Ah[fm], Bl[fn]);
                    mma_bf16(acc[fm][fn], Al[fm], Bh[fn]);
                }
        }
        __syncthreads();
    }

    // Epilogue: acc c0,c1 -> (row, col..col+1); c2,c3 -> (row+8, ...)
    #pragma unroll
    for (int fm = 0; fm < 4; ++fm) {
        int gm = mt * 128 + wm * 64 + fm * 16 + (lane >> 2);
        #pragma unroll
        for (int fn = 0; fn < 4; ++fn) {
            int gn = nt * 128 + wn * 32 + fn * 8 + (lane & 3) * 2;
            if (gn < NITEMS) {   // gn even, NITEMS even -> pair fully valid
                float2 bv = __ldg((const float2*)(bout + gn));
                float2 o0 = make_float2(acc[fm][fn][0] + bv.x, acc[fm][fn][1] + bv.y);
                float2 o1 = make_float2(acc[fm][fn][2] + bv.x, acc[fm][fn][3] + bv.y);
                *(float2*)(out + (size_t)gm * NITEMS + gn) = o0;
                *(float2*)(out + (size_t)(gm + 8) * NITEMS + gn) = o1;
            }
        }
    }
}

// ---------------------------------------------------------------------------
extern "C" void kernel_launch(void* const* d_in, const int* in_sizes, int n_in,
                              void* d_out, int out_size) {
    const int*   q    = (const int*)  d_in[0];
    const int*   f    = (const int*)  d_in[1];
    const float* eq   = (const float*)d_in[2];
    const float* ef   = (const float*)d_in[3];
    const float* ic   = (const float*)d_in[4];
    const float* Wi   = (const float*)d_in[5];
    const float* bi   = (const float*)d_in[6];
    const float* Wh   = (const float*)d_in[7];
    const float* bhn  = (const float*)d_in[8];
    const float* Wout = (const float*)d_in[9];
    const float* bout = (const float*)d_in[10];
    float* out = (float*)d_out;

    static bool attr_done = false;
    if (!attr_done) {
        cudaFuncSetAttribute(k_gi,      cudaFuncAttributeMaxDynamicSharedMemorySize, K2_SMEM);
        cudaFuncSetAttribute(k_out_mma, cudaFuncAttributeMaxDynamicSharedMemorySize, MMA_SMEM);
        attr_done = true;
    }

    // Wout -> bf16 hi/lo [256][100096] (independent)
    {
        dim3 grid((NPADW / 8 + 255) / 256, KPAD);
        k_cvt_w<<<grid, 256>>>(Wout);
    }
    // GI = (gathered state) @ Wi + bi for all t
    {
        dim3 grid(8, 5, 200);
        k_gi<<<grid, 256, K2_SMEM>>>(q, f, eq, ef, Wi, bi);
    }
    // GRU scan
    k_scan<<<128, 640>>>(Wh, bhn, ic);
    // hT -> bf16 hi/lo [1024][256]
    k_cvt_h<<<(B_ * 32 + 255) / 256, 256>>>();
    // out = hT @ Wout + bout  (mma.sync tensor cores)
    {
        dim3 grid(8, NT2);
        k_out_mma<<<grid, 256, MMA_SMEM>>>(bout, out);
    }
}